// round 1
// baseline (speedup 1.0000x reference)
#include <cuda_runtime.h>
#include <math.h>

// Problem constants
#define NB 8
#define NT 512
#define NTOK 4096   // NB*NT tokens

// Scratch buffers (static device globals — no runtime allocation allowed)
__device__ float g_x   [NTOK * 1024];   // x = lnsilu(act@W_pre)+emb@W_emb   [T,B,HID]
__device__ float g_xz  [NTOK * 2048];   // xz = x@W_in+b  (ssm | gate)
__device__ float g_dt  [NTOK * 1024];   // softplus(x_ssm@W_dt+b_dt)
__device__ float g_bc  [NTOK * 32];     // Bp (16) | Cp (16)
__device__ float g_y   [NTOK * 1024];   // scan output (gated)
__device__ float g_det [NTOK * 1024];   // deter
__device__ float g_tmp [NTOK * 1024];   // pre-LN GEMM outputs / post logits
__device__ float g_h1  [NTOK * 1024];   // hidden after lnsilu

// ---------------------------------------------------------------------------
// Generic fp32 GEMM: C[M=4096, N] = act( A[M,K] @ W[K,N] + bias ) (+ addend)
// A is split: cols [0,K0) from A0 (row p, stride lda0),
//             cols [K0,K) from A1 with token gather row (p%8)*512 + p/8
// BM=128, BN=64, BK=16, 256 threads, 8x4 per-thread microtile.
// ---------------------------------------------------------------------------
__global__ __launch_bounds__(256, 2) void gemm_kernel(
    const float* __restrict__ A0, int lda0, int K0,
    const float* __restrict__ A1, int lda1,
    const float* __restrict__ W,
    const float* __restrict__ bias,
    const float* __restrict__ addend, int ldadd,
    float* __restrict__ C, int ldc,
    int N, int K, int act)
{
    __shared__ float As[16][128];
    __shared__ float Bs[16][68];   // padded row to de-conflict stores

    const int tid = threadIdx.x;
    const int tx  = tid & 15;       // N direction (16 * 4 = 64)
    const int ty  = tid >> 4;       // M direction (16 * 8 = 128)
    const int bm  = blockIdx.y * 128;
    const int bn  = blockIdx.x * 64;

    // A tile load mapping: thread -> (row, 8-wide K chunk)
    const int arow = tid >> 1;            // 0..127
    const int akk  = (tid & 1) * 8;       // 0 or 8
    // B tile load mapping: thread -> (k row, 4-wide N chunk)
    const int brow = tid >> 4;            // 0..15
    const int bcol = (tid & 15) * 4;      // 0..60

    const int grow = bm + arow;           // global token row for A loads
    const int gt = grow >> 3;             // t
    const int gb = grow & 7;              // b

    float acc[8][4];
    #pragma unroll
    for (int i = 0; i < 8; i++)
        #pragma unroll
        for (int j = 0; j < 4; j++) acc[i][j] = 0.f;

    for (int k0 = 0; k0 < K; k0 += 16) {
        // ---- load A tile (transposed into smem) ----
        const float* asrc;
        if (k0 < K0) asrc = A0 + (size_t)grow * lda0 + (k0 + akk);
        else         asrc = A1 + (size_t)(gb * NT + gt) * lda1 + (k0 - K0 + akk);
        float4 av0 = *(const float4*)asrc;
        float4 av1 = *(const float4*)(asrc + 4);

        // ---- load B tile ----
        const float* wsrc = W + (size_t)(k0 + brow) * N + (bn + bcol);
        float4 wv;
        if (bn + bcol + 3 < N) {
            wv = *(const float4*)wsrc;
        } else {
            wv.x = (bn + bcol + 0 < N) ? wsrc[0] : 0.f;
            wv.y = (bn + bcol + 1 < N) ? wsrc[1] : 0.f;
            wv.z = (bn + bcol + 2 < N) ? wsrc[2] : 0.f;
            wv.w = (bn + bcol + 3 < N) ? wsrc[3] : 0.f;
        }

        As[akk + 0][arow] = av0.x; As[akk + 1][arow] = av0.y;
        As[akk + 2][arow] = av0.z; As[akk + 3][arow] = av0.w;
        As[akk + 4][arow] = av1.x; As[akk + 5][arow] = av1.y;
        As[akk + 6][arow] = av1.z; As[akk + 7][arow] = av1.w;
        *(float4*)&Bs[brow][bcol] = wv;

        __syncthreads();

        #pragma unroll
        for (int kk = 0; kk < 16; kk++) {
            float4 a0 = *(const float4*)&As[kk][ty * 8];
            float4 a1 = *(const float4*)&As[kk][ty * 8 + 4];
            float4 b4 = *(const float4*)&Bs[kk][tx * 4];
            float ar[8] = {a0.x, a0.y, a0.z, a0.w, a1.x, a1.y, a1.z, a1.w};
            float br[4] = {b4.x, b4.y, b4.z, b4.w};
            #pragma unroll
            for (int i = 0; i < 8; i++)
                #pragma unroll
                for (int j = 0; j < 4; j++)
                    acc[i][j] = fmaf(ar[i], br[j], acc[i][j]);
        }
        __syncthreads();
    }

    // ---- epilogue ----
    float bv[4];
    #pragma unroll
    for (int j = 0; j < 4; j++) {
        int col = bn + tx * 4 + j;
        bv[j] = (bias != nullptr && col < N) ? bias[col] : 0.f;
    }
    #pragma unroll
    for (int i = 0; i < 8; i++) {
        int row = bm + ty * 8 + i;
        #pragma unroll
        for (int j = 0; j < 4; j++) {
            int col = bn + tx * 4 + j;
            if (col < N) {
                float v = acc[i][j] + bv[j];
                if (addend) v += addend[(size_t)row * ldadd + col];
                if (act == 1)  // softplus (stable)
                    v = fmaxf(v, 0.f) + log1pf(__expf(-fabsf(v)));
                C[(size_t)row * ldc + col] = v;
            }
        }
    }
}

// ---------------------------------------------------------------------------
// Stage 0: per-token  lnsilu(actions @ W_pre + b_pre)  -> g_x
// One block per token (in [T,B] order), 256 threads, 4 cols each.
// ---------------------------------------------------------------------------
__global__ __launch_bounds__(256) void pre_kernel(
    const float* __restrict__ actions, const float* __restrict__ W_pre,
    const float* __restrict__ b_pre, const float* __restrict__ g_pre,
    const float* __restrict__ bb_pre, float* __restrict__ xout)
{
    int p = blockIdx.x;
    int t = p >> 3, b = p & 7;
    __shared__ float sa[32];
    __shared__ float red[2][8];
    int tid = threadIdx.x;
    if (tid < 32) sa[tid] = actions[(size_t)(b * NT + t) * 32 + tid];
    __syncthreads();

    int c0 = tid * 4;
    float4 acc = *(const float4*)(b_pre + c0);
    #pragma unroll 8
    for (int k = 0; k < 32; k++) {
        float a = sa[k];
        float4 w = *(const float4*)(W_pre + (size_t)k * 1024 + c0);
        acc.x = fmaf(a, w.x, acc.x); acc.y = fmaf(a, w.y, acc.y);
        acc.z = fmaf(a, w.z, acc.z); acc.w = fmaf(a, w.w, acc.w);
    }
    float s  = acc.x + acc.y + acc.z + acc.w;
    float s2 = acc.x*acc.x + acc.y*acc.y + acc.z*acc.z + acc.w*acc.w;
    #pragma unroll
    for (int o = 16; o; o >>= 1) {
        s  += __shfl_xor_sync(0xffffffffu, s, o);
        s2 += __shfl_xor_sync(0xffffffffu, s2, o);
    }
    if ((tid & 31) == 0) { red[0][tid >> 5] = s; red[1][tid >> 5] = s2; }
    __syncthreads();
    if (tid == 0) {
        float a = 0.f, c = 0.f;
        for (int i = 0; i < 8; i++) { a += red[0][i]; c += red[1][i]; }
        red[0][0] = a; red[1][0] = c;
    }
    __syncthreads();
    float mean = red[0][0] * (1.f / 1024.f);
    float var  = red[1][0] * (1.f / 1024.f) - mean * mean;
    float inv  = rsqrtf(var + 1e-5f);
    float vv[4] = {acc.x, acc.y, acc.z, acc.w};
    #pragma unroll
    for (int j = 0; j < 4; j++) {
        int c = c0 + j;
        float xn = (vv[j] - mean) * inv * g_pre[c] + bb_pre[c];
        xn = xn * (1.f / (1.f + __expf(-xn)));   // silu
        xout[(size_t)p * 1024 + c] = xn;
    }
}

// ---------------------------------------------------------------------------
// Per-token LayerNorm (+optional silu), row width 1024.
// Writes Y (and optionally Y2 with its own stride — used for deter -> output).
// ---------------------------------------------------------------------------
__global__ __launch_bounds__(256) void ln_kernel(
    const float* __restrict__ X,
    const float* __restrict__ gma, const float* __restrict__ bta,
    float* __restrict__ Y, int ldy,
    float* __restrict__ Y2, int ldy2,
    int dosilu)
{
    int p = blockIdx.x;
    int tid = threadIdx.x;
    int c0 = tid * 4;
    __shared__ float red[2][8];
    float4 v = *(const float4*)(X + (size_t)p * 1024 + c0);
    float s  = v.x + v.y + v.z + v.w;
    float s2 = v.x*v.x + v.y*v.y + v.z*v.z + v.w*v.w;
    #pragma unroll
    for (int o = 16; o; o >>= 1) {
        s  += __shfl_xor_sync(0xffffffffu, s, o);
        s2 += __shfl_xor_sync(0xffffffffu, s2, o);
    }
    if ((tid & 31) == 0) { red[0][tid >> 5] = s; red[1][tid >> 5] = s2; }
    __syncthreads();
    if (tid == 0) {
        float a = 0.f, c = 0.f;
        for (int i = 0; i < 8; i++) { a += red[0][i]; c += red[1][i]; }
        red[0][0] = a; red[1][0] = c;
    }
    __syncthreads();
    float mean = red[0][0] * (1.f / 1024.f);
    float var  = red[1][0] * (1.f / 1024.f) - mean * mean;
    float inv  = rsqrtf(var + 1e-5f);
    float vv[4] = {v.x, v.y, v.z, v.w};
    #pragma unroll
    for (int j = 0; j < 4; j++) {
        int c = c0 + j;
        float xn = (vv[j] - mean) * inv * gma[c] + bta[c];
        if (dosilu) xn = xn * (1.f / (1.f + __expf(-xn)));
        Y[(size_t)p * ldy + c] = xn;
        if (Y2) Y2[(size_t)p * ldy2 + c] = xn;
    }
}

// ---------------------------------------------------------------------------
// SSM scan: channel (b,d) handled by a 16-lane group (lane = state n).
// h_t = exp(dt*A)*h_{t-1} + dt*x_ssm*Bp ;  y = <h,Cp> + Dp*x_ssm ; gated silu.
// 131072 threads total (4096 warps) -> plenty of latency hiding.
// ---------------------------------------------------------------------------
__global__ __launch_bounds__(256) void scan_kernel(
    const float* __restrict__ xz, const float* __restrict__ dt,
    const float* __restrict__ bc, const float* __restrict__ A_log,
    const float* __restrict__ Dp, float* __restrict__ y)
{
    int pair = blockIdx.x * 16 + (threadIdx.x >> 4);   // (b,d): pair = b*1024 + d
    int n = threadIdx.x & 15;
    int b = pair >> 10;
    int d = pair & 1023;
    float A  = -__expf(A_log[d * 16 + n]);
    float Dd = Dp[d];
    float h = 0.f;
    for (int t = 0; t < NT; t++) {
        int p = t * NB + b;
        float dtv = dt[(size_t)p * 1024 + d];
        float xs  = xz[(size_t)p * 2048 + d];
        float g   = __expf(dtv * A);
        h = fmaf(g, h, dtv * xs * bc[(size_t)p * 32 + n]);
        float c = h * bc[(size_t)p * 32 + 16 + n];
        c += __shfl_xor_sync(0xffffffffu, c, 8, 16);
        c += __shfl_xor_sync(0xffffffffu, c, 4, 16);
        c += __shfl_xor_sync(0xffffffffu, c, 2, 16);
        c += __shfl_xor_sync(0xffffffffu, c, 1, 16);
        if (n == 0) {
            float gate = xz[(size_t)p * 2048 + 1024 + d];
            y[(size_t)p * 1024 + d] =
                (c + Dd * xs) * gate * (1.f / (1.f + __expf(-gate)));
        }
    }
}

// ---------------------------------------------------------------------------
// softmax over CLS=32 chunks + unimix + log -> out[:, 2048:3072]
// One warp per (token, stochastic slot).
// ---------------------------------------------------------------------------
__global__ __launch_bounds__(256) void softmax_kernel(
    const float* __restrict__ post, float* __restrict__ out)
{
    int idx  = blockIdx.x * 8 + (threadIdx.x >> 5);
    int lane = threadIdx.x & 31;
    int p = idx >> 5, s = idx & 31;
    float v = post[(size_t)p * 1024 + s * 32 + lane];
    float m = v;
    #pragma unroll
    for (int o = 16; o; o >>= 1) m = fmaxf(m, __shfl_xor_sync(0xffffffffu, m, o));
    float e = __expf(v - m);
    float sum = e;
    #pragma unroll
    for (int o = 16; o; o >>= 1) sum += __shfl_xor_sync(0xffffffffu, sum, o);
    float prob = e / sum;
    out[(size_t)p * 3072 + 2048 + s * 32 + lane] =
        logf(0.99f * prob + 0.01f / 32.f + 1e-8f);
}

// ---------------------------------------------------------------------------
extern "C" void kernel_launch(void* const* d_in, const int* in_sizes, int n_in,
                              void* d_out, int out_size)
{
    const float* actions = (const float*)d_in[0];
    const float* embeds  = (const float*)d_in[1];
    const float* W_pre   = (const float*)d_in[2];
    const float* b_pre   = (const float*)d_in[3];
    const float* g_pre   = (const float*)d_in[4];
    const float* bb_pre  = (const float*)d_in[5];
    const float* W_emb   = (const float*)d_in[6];
    const float* W_in    = (const float*)d_in[7];
    const float* b_in    = (const float*)d_in[8];
    const float* W_dt    = (const float*)d_in[9];
    const float* b_dt    = (const float*)d_in[10];
    const float* W_B     = (const float*)d_in[11];
    const float* W_C     = (const float*)d_in[12];
    const float* A_log   = (const float*)d_in[13];
    const float* Dp      = (const float*)d_in[14];
    const float* g_out   = (const float*)d_in[15];
    const float* b_out   = (const float*)d_in[16];
    const float* W_pr1   = (const float*)d_in[17];
    const float* b_pr1   = (const float*)d_in[18];
    const float* g_pr    = (const float*)d_in[19];
    const float* bb_pr   = (const float*)d_in[20];
    const float* W_pr2   = (const float*)d_in[21];
    const float* b_pr2   = (const float*)d_in[22];
    const float* W_po1   = (const float*)d_in[23];
    const float* b_po1   = (const float*)d_in[24];
    const float* g_po    = (const float*)d_in[25];
    const float* bb_po   = (const float*)d_in[26];
    const float* W_po2   = (const float*)d_in[27];
    const float* b_po2   = (const float*)d_in[28];
    float* out = (float*)d_out;

    float *px, *pxz, *pdt, *pbc, *py, *pdet, *ptmp, *ph;
    cudaGetSymbolAddress((void**)&px,   g_x);
    cudaGetSymbolAddress((void**)&pxz,  g_xz);
    cudaGetSymbolAddress((void**)&pdt,  g_dt);
    cudaGetSymbolAddress((void**)&pbc,  g_bc);
    cudaGetSymbolAddress((void**)&py,   g_y);
    cudaGetSymbolAddress((void**)&pdet, g_det);
    cudaGetSymbolAddress((void**)&ptmp, g_tmp);
    cudaGetSymbolAddress((void**)&ph,   g_h1);

    dim3 blk(256);
    dim3 gN1(1024 / 64, NTOK / 128);   // N=1024
    dim3 gN2(2048 / 64, NTOK / 128);   // N=2048
    dim3 gNs(1,         NTOK / 128);   // N<=64

    // 0: lnsilu(actions @ W_pre + b_pre) -> g_x
    pre_kernel<<<NTOK, blk>>>(actions, W_pre, b_pre, g_pre, bb_pre, px);

    // 1: g_x += embeds(gathered) @ W_emb
    gemm_kernel<<<gN1, blk>>>(nullptr, 0, 0, embeds, 1024, W_emb,
                              nullptr, px, 1024, px, 1024, 1024, 1024, 0);

    // 2: xz = x @ W_in + b_in
    gemm_kernel<<<gN2, blk>>>(px, 1024, 1024, nullptr, 0, W_in,
                              b_in, nullptr, 0, pxz, 2048, 2048, 1024, 0);

    // 3: dt = softplus(x_ssm @ W_dt + b_dt)
    gemm_kernel<<<gN1, blk>>>(pxz, 2048, 1024, nullptr, 0, W_dt,
                              b_dt, nullptr, 0, pdt, 1024, 1024, 1024, 1);

    // 4: Bp, Cp
    gemm_kernel<<<gNs, blk>>>(pxz, 2048, 1024, nullptr, 0, W_B,
                              nullptr, nullptr, 0, pbc, 32, 16, 1024, 0);
    gemm_kernel<<<gNs, blk>>>(pxz, 2048, 1024, nullptr, 0, W_C,
                              nullptr, nullptr, 0, pbc + 16, 32, 16, 1024, 0);

    // 5: SSM scan + gate -> g_y
    scan_kernel<<<512, blk>>>(pxz, pdt, pbc, A_log, Dp, py);

    // 6: deter = LN(y); write g_det and out[:, 0:1024]
    ln_kernel<<<NTOK, blk>>>(py, g_out, b_out, pdet, 1024, out, 3072, 0);

    // 7: prior head
    gemm_kernel<<<gN1, blk>>>(pdet, 1024, 1024, nullptr, 0, W_pr1,
                              b_pr1, nullptr, 0, ptmp, 1024, 1024, 1024, 0);
    ln_kernel<<<NTOK, blk>>>(ptmp, g_pr, bb_pr, ph, 1024, nullptr, 0, 1);
    gemm_kernel<<<gN1, blk>>>(ph, 1024, 1024, nullptr, 0, W_pr2,
                              b_pr2, nullptr, 0, out + 1024, 3072, 1024, 1024, 0);

    // 8: post head (post_in = [deter | emb_t], K=2048)
    gemm_kernel<<<gN1, blk>>>(pdet, 1024, 1024, embeds, 1024, W_po1,
                              b_po1, nullptr, 0, ptmp, 1024, 1024, 2048, 0);
    ln_kernel<<<NTOK, blk>>>(ptmp, g_po, bb_po, ph, 1024, nullptr, 0, 1);
    gemm_kernel<<<gN1, blk>>>(ph, 1024, 1024, nullptr, 0, W_po2,
                              b_po2, nullptr, 0, ptmp, 1024, 1024, 1024, 0);

    // 9: softmax + unimix + log -> out[:, 2048:3072]
    softmax_kernel<<<NTOK * 32 / 8, blk>>>(ptmp, out);
}